// round 3
// baseline (speedup 1.0000x reference)
#include <cuda_runtime.h>
#include <cuda_bf16.h>
#include <cstdint>

// LocalSelfAttention (bs=4,h=12,s=4096,d=64,block=64), sm_100 mma.sync path.
// Per CTA: one 64x64 block. bf16 hi/lo 3x-split GEMMs via m16n8k16.
// Q/K/V staged into smem in *fragment order* -> inner loops are conflict-free LDS.128.
// P stays in registers between the two GEMMs.

#define OFF_QA 0          // [kt4][aslot2][w4][lane32][16B] = 16384
#define OFF_KB 16384      // [kt4][nt8][lane32][16B]        = 16384
#define OFF_VB 32768      // [kt4][nt8][lane32][16B]        = 16384
#define OFF_KBIAS 49152   // 64 f32 key-side additive bias
#define OFF_QM 49408      // 64 f32 query mask
#define SM_BYTES 49664

__device__ __forceinline__ uint32_t s2u(const void* p) {
    uint32_t a;
    asm("{ .reg .u64 t; cvta.to.shared.u64 t, %1; cvt.u32.u64 %0, t; }" : "=r"(a) : "l"(p));
    return a;
}
// pack two f32 -> bf16x2 word: low half = first arg
__device__ __forceinline__ uint32_t pk(float lo, float hi) {
    uint32_t r;
    asm("cvt.rn.bf16x2.f32 %0, %2, %1;" : "=r"(r) : "f"(lo), "f"(hi));
    return r;
}
__device__ __forceinline__ float bfr(float x) {   // residual x - bf16(x)
    return x - __bfloat162float(__float2bfloat16(x));
}
__device__ __forceinline__ void sts64(uint32_t a, uint32_t x, uint32_t y) {
    asm volatile("st.shared.v2.b32 [%0], {%1,%2};" :: "r"(a), "r"(x), "r"(y));
}
__device__ __forceinline__ void lds128(uint32_t a, uint32_t& x, uint32_t& y, uint32_t& z, uint32_t& w) {
    asm volatile("ld.shared.v4.b32 {%0,%1,%2,%3}, [%4];" : "=r"(x), "=r"(y), "=r"(z), "=r"(w) : "r"(a));
}
__device__ __forceinline__ void mma16(float* d,
                                      uint32_t a0, uint32_t a1, uint32_t a2, uint32_t a3,
                                      uint32_t b0, uint32_t b1) {
    asm volatile(
        "mma.sync.aligned.m16n8k16.row.col.f32.bf16.bf16.f32 "
        "{%0,%1,%2,%3}, {%4,%5,%6,%7}, {%8,%9}, {%0,%1,%2,%3};"
        : "+f"(d[0]), "+f"(d[1]), "+f"(d[2]), "+f"(d[3])
        : "r"(a0), "r"(a1), "r"(a2), "r"(a3), "r"(b0), "r"(b1));
}

__global__ void __launch_bounds__(128, 4) lsa3_kernel(
    const float* __restrict__ Qg_, const float* __restrict__ Kg_,
    const float* __restrict__ Vg_, const float* __restrict__ Mg_,
    float* __restrict__ Og_)
{
    extern __shared__ __align__(1024) char sm[];
    const uint32_t sb = s2u(sm);
    const int tid = threadIdx.x;
    const int blk = blockIdx.x;
    const size_t base = (size_t)blk * 4096;

    // ---- mask staging ----
    if (tid < 64) {
        int b  = blk / 768;
        int nb = blk & 63;
        float m = Mg_[(size_t)b * 4096 + (size_t)(nb * 64 + tid)];
        *(float*)(sm + OFF_KBIAS + tid * 4) = (m == 0.0f) ? -10000.0f : 0.0f;
        *(float*)(sm + OFF_QM + tid * 4) = m;
    }

    // ---- stage Q,K into fragment-order smem (bf16 hi/lo) ----
    const float4* Qg = (const float4*)(Qg_ + base);
    const float4* Kg = (const float4*)(Kg_ + base);
    const float4* Vg = (const float4*)(Vg_ + base);
    #pragma unroll
    for (int it = 0; it < 8; it++) {
        int i = tid + it * 128;           // 0..1023
        int r = i >> 4;                   // row 0..63
        int c = (i & 15) << 2;            // col 0..60
        float4 q = Qg[i], k = Kg[i];
        int p0 = c >> 1;                  // bf16x2 pair index (even)
        uint32_t qrow = sb + OFF_QA + (uint32_t)(((r >> 3) & 1) * 2048 + (r >> 4) * 512 + (r & 7) * 64);
        uint32_t krow = sb + OFF_KB + (uint32_t)((r >> 3) * 512 + (r & 7) * 64);
        #pragma unroll
        for (int pp = 0; pp < 2; pp++) {
            int p   = p0 + pp;
            float x  = pp ? q.z : q.x, y  = pp ? q.w : q.y;
            float kx = pp ? k.z : k.x, ky = pp ? k.w : k.y;
            uint32_t po = (uint32_t)((p >> 3) * 4096 + (p & 3) * 16 + ((p >> 2) & 1) * 8);
            sts64(qrow + po, pk(x, y),   pk(bfr(x),  bfr(y)));
            sts64(krow + po, pk(kx, ky), pk(bfr(kx), bfr(ky)));
        }
    }
    // ---- stage V (k-dim = keys: pack key pairs) ----
    #pragma unroll
    for (int it = 0; it < 4; it++) {
        int j  = tid + it * 128;          // 0..511
        int kp = j >> 4;                  // key pair 0..31
        int mi = j & 15;
        int c  = mi << 2;                 // d = c..c+3
        float4 va = Vg[kp * 32 + mi];     // key 2kp
        float4 vb = Vg[kp * 32 + 16 + mi];// key 2kp+1
        uint32_t vkb = sb + OFF_VB +
            (uint32_t)((kp >> 3) * 4096 + (kp & 3) * 16 + ((kp >> 2) & 1) * 8);
        const float* pa = (const float*)&va;
        const float* pb = (const float*)&vb;
        #pragma unroll
        for (int j2 = 0; j2 < 4; j2++) {
            int d = c + j2;
            uint32_t addr = vkb + (uint32_t)((d >> 3) * 512 + (d & 7) * 64);
            sts64(addr, pk(pa[j2], pb[j2]), pk(bfr(pa[j2]), bfr(pb[j2])));
        }
    }
    __syncthreads();

    const int w    = tid >> 5;
    const int lane = tid & 31;
    const int g    = lane >> 2;
    const int t    = lane & 3;
    const int mb   = w * 16;

    float acc[8][4];
    #pragma unroll
    for (int nt = 0; nt < 8; nt++) {
        acc[nt][0] = 0.f; acc[nt][1] = 0.f; acc[nt][2] = 0.f; acc[nt][3] = 0.f;
    }

    // ---- S = Q K^T : 3x bf16 split, conflict-free LDS.128 fragments ----
    {
        uint32_t qa = sb + OFF_QA + (uint32_t)(w * 512 + lane * 16);
        uint32_t kb = sb + OFF_KB + (uint32_t)(lane * 16);
        #pragma unroll
        for (int kt = 0; kt < 4; kt++) {
            uint32_t a0h, a0l, a2h, a2l, a1h, a1l, a3h, a3l;
            lds128(qa + kt * 4096,        a0h, a0l, a2h, a2l);   // row mb+g
            lds128(qa + kt * 4096 + 2048, a1h, a1l, a3h, a3l);   // row mb+8+g
            #pragma unroll
            for (int nt = 0; nt < 8; nt++) {
                uint32_t b0h, b0l, b1h, b1l;
                lds128(kb + (uint32_t)(kt * 4096 + nt * 512), b0h, b0l, b1h, b1l);
                mma16(acc[nt], a0h, a1h, a2h, a3h, b0h, b1h);
                mma16(acc[nt], a0h, a1h, a2h, a3h, b0l, b1l);
                mma16(acc[nt], a0l, a1l, a2l, a3l, b0h, b1h);
            }
        }
    }

    // ---- softmax (rows in-warp, quad shuffles) ----
    const float* kbias = (const float*)(sm + OFF_KBIAS);
    const float* qm    = (const float*)(sm + OFF_QM);
    float m0 = -3.0e38f, m1 = -3.0e38f;
    #pragma unroll
    for (int nt = 0; nt < 8; nt++) {
        float2 kbv = *(const float2*)&kbias[nt * 8 + 2 * t];
        acc[nt][0] += kbv.x; acc[nt][1] += kbv.y;
        acc[nt][2] += kbv.x; acc[nt][3] += kbv.y;
        m0 = fmaxf(m0, fmaxf(acc[nt][0], acc[nt][1]));
        m1 = fmaxf(m1, fmaxf(acc[nt][2], acc[nt][3]));
    }
    m0 = fmaxf(m0, __shfl_xor_sync(0xffffffffu, m0, 1));
    m0 = fmaxf(m0, __shfl_xor_sync(0xffffffffu, m0, 2));
    m1 = fmaxf(m1, __shfl_xor_sync(0xffffffffu, m1, 1));
    m1 = fmaxf(m1, __shfl_xor_sync(0xffffffffu, m1, 2));
    float s0 = 0.f, s1 = 0.f;
    #pragma unroll
    for (int nt = 0; nt < 8; nt++) {
        acc[nt][0] = __expf(acc[nt][0] - m0);
        acc[nt][1] = __expf(acc[nt][1] - m0);
        acc[nt][2] = __expf(acc[nt][2] - m1);
        acc[nt][3] = __expf(acc[nt][3] - m1);
        s0 += acc[nt][0] + acc[nt][1];
        s1 += acc[nt][2] + acc[nt][3];
    }
    s0 += __shfl_xor_sync(0xffffffffu, s0, 1);
    s0 += __shfl_xor_sync(0xffffffffu, s0, 2);
    s1 += __shfl_xor_sync(0xffffffffu, s1, 1);
    s1 += __shfl_xor_sync(0xffffffffu, s1, 2);
    float r0 = (qm[mb + g]     == 0.0f) ? 0.0f : (1.0f / s0);
    float r1 = (qm[mb + g + 8] == 0.0f) ? 0.0f : (1.0f / s1);

    // ---- O = P V : P straight from registers (hi/lo packed), V fragments LDS.128 ----
    float accO[8][4];
    #pragma unroll
    for (int nt = 0; nt < 8; nt++) {
        accO[nt][0] = 0.f; accO[nt][1] = 0.f; accO[nt][2] = 0.f; accO[nt][3] = 0.f;
    }
    {
        uint32_t vbb = sb + OFF_VB + (uint32_t)(lane * 16);
        #pragma unroll
        for (int kt = 0; kt < 4; kt++) {
            float s00 = acc[2*kt][0]   * r0, s01 = acc[2*kt][1]   * r0;
            float s10 = acc[2*kt][2]   * r1, s11 = acc[2*kt][3]   * r1;
            float s20 = acc[2*kt+1][0] * r0, s21 = acc[2*kt+1][1] * r0;
            float s30 = acc[2*kt+1][2] * r1, s31 = acc[2*kt+1][3] * r1;
            uint32_t a0h = pk(s00, s01), a1h = pk(s10, s11);
            uint32_t a2h = pk(s20, s21), a3h = pk(s30, s31);
            uint32_t a0l = pk(bfr(s00), bfr(s01)), a1l = pk(bfr(s10), bfr(s11));
            uint32_t a2l = pk(bfr(s20), bfr(s21)), a3l = pk(bfr(s30), bfr(s31));
            #pragma unroll
            for (int nt = 0; nt < 8; nt++) {
                uint32_t b0h, b0l, b1h, b1l;
                lds128(vbb + (uint32_t)(kt * 4096 + nt * 512), b0h, b0l, b1h, b1l);
                mma16(accO[nt], a0h, a1h, a2h, a3h, b0h, b1h);
                mma16(accO[nt], a0h, a1h, a2h, a3h, b0l, b1l);
                mma16(accO[nt], a0l, a1l, a2l, a3l, b0h, b1h);
            }
        }
    }

    // ---- store O (sector-aligned float2) ----
    float* Og = Og_ + base;
    #pragma unroll
    for (int nt = 0; nt < 8; nt++) {
        *(float2*)&Og[(mb + g)     * 64 + nt * 8 + 2 * t] = make_float2(accO[nt][0], accO[nt][1]);
        *(float2*)&Og[(mb + g + 8) * 64 + nt * 8 + 2 * t] = make_float2(accO[nt][2], accO[nt][3]);
    }
}

extern "C" void kernel_launch(void* const* d_in, const int* in_sizes, int n_in,
                              void* d_out, int out_size) {
    const float* Q = (const float*)d_in[0];
    const float* K = (const float*)d_in[1];
    const float* V = (const float*)d_in[2];
    const float* M = (const float*)d_in[3];
    float* O = (float*)d_out;
    cudaFuncSetAttribute(lsa3_kernel, cudaFuncAttributeMaxDynamicSharedMemorySize, SM_BYTES);
    lsa3_kernel<<<3072, 128, SM_BYTES>>>(Q, K, V, M, O);
}

// round 4
// speedup vs baseline: 1.8174x; 1.8174x over previous
#include <cuda_runtime.h>
#include <cuda_bf16.h>
#include <cstdint>

// LocalSelfAttention (bs=4,h=12,s=4096,d=64,block=64), sm_100 mma.sync path.
// Per CTA: one 64x64 block. bf16 hi/lo 3x-split GEMMs via m16n8k16.
// Q: direct LDG fragments (no smem). K,V: row-major SW-swizzled smem, conflict-free
// STS.64 staging, fragments gathered by ldmatrix.x4 (non-trans for K, trans for V).
// P stays in registers between the two GEMMs.

#define OFF_KH 0          // K hi plane: 64 rows x 128B
#define OFF_KL 8192       // K lo plane
#define OFF_VH 16384      // V hi plane
#define OFF_VL 24576      // V lo plane
#define OFF_KB 32768      // 64 f32 key-side additive bias
#define OFF_QM 33024      // 64 f32 query mask
#define SM_BYTES 33280

__device__ __forceinline__ uint32_t s2u(const void* p) {
    uint32_t a;
    asm("{ .reg .u64 t; cvta.to.shared.u64 t, %1; cvt.u32.u64 %0, t; }" : "=r"(a) : "l"(p));
    return a;
}
// pack two f32 -> bf16x2 word: low half = first arg
__device__ __forceinline__ uint32_t pk(float lo, float hi) {
    uint32_t r;
    asm("cvt.rn.bf16x2.f32 %0, %2, %1;" : "=r"(r) : "f"(lo), "f"(hi));
    return r;
}
__device__ __forceinline__ float bfr(float x) {   // residual x - bf16(x)
    return x - __bfloat162float(__float2bfloat16(x));
}
__device__ __forceinline__ void sts64(uint32_t a, uint32_t x, uint32_t y) {
    asm volatile("st.shared.v2.b32 [%0], {%1,%2};" :: "r"(a), "r"(x), "r"(y));
}
__device__ __forceinline__ void ldmx4(uint32_t a, uint32_t& r0, uint32_t& r1, uint32_t& r2, uint32_t& r3) {
    asm volatile("ldmatrix.sync.aligned.m8n8.x4.shared.b16 {%0,%1,%2,%3}, [%4];"
                 : "=r"(r0), "=r"(r1), "=r"(r2), "=r"(r3) : "r"(a));
}
__device__ __forceinline__ void ldmx4t(uint32_t a, uint32_t& r0, uint32_t& r1, uint32_t& r2, uint32_t& r3) {
    asm volatile("ldmatrix.sync.aligned.m8n8.x4.trans.shared.b16 {%0,%1,%2,%3}, [%4];"
                 : "=r"(r0), "=r"(r1), "=r"(r2), "=r"(r3) : "r"(a));
}
__device__ __forceinline__ void mma16(float* d,
                                      uint32_t a0, uint32_t a1, uint32_t a2, uint32_t a3,
                                      uint32_t b0, uint32_t b1) {
    asm volatile(
        "mma.sync.aligned.m16n8k16.row.col.f32.bf16.bf16.f32 "
        "{%0,%1,%2,%3}, {%4,%5,%6,%7}, {%8,%9}, {%0,%1,%2,%3};"
        : "+f"(d[0]), "+f"(d[1]), "+f"(d[2]), "+f"(d[3])
        : "r"(a0), "r"(a1), "r"(a2), "r"(a3), "r"(b0), "r"(b1));
}

__global__ void __launch_bounds__(128, 4) lsa4_kernel(
    const float* __restrict__ Qg_, const float* __restrict__ Kg_,
    const float* __restrict__ Vg_, const float* __restrict__ Mg_,
    float* __restrict__ Og_)
{
    extern __shared__ __align__(1024) char sm[];
    const uint32_t sb = s2u(sm);
    const int tid = threadIdx.x;
    const int blk = blockIdx.x;
    const size_t base = (size_t)blk * 4096;

    // ---- mask staging ----
    if (tid < 64) {
        int b  = blk / 768;
        int nb = blk & 63;
        float m = Mg_[(size_t)b * 4096 + (size_t)(nb * 64 + tid)];
        *(float*)(sm + OFF_KB + tid * 4) = (m == 0.0f) ? -10000.0f : 0.0f;
        *(float*)(sm + OFF_QM + tid * 4) = m;
    }

    // ---- stage K,V row-major bf16 hi/lo with XOR swizzle (conflict-free STS.64) ----
    const float4* Kg = (const float4*)(Kg_ + base);
    const float4* Vg = (const float4*)(Vg_ + base);
    #pragma unroll
    for (int it = 0; it < 8; it++) {
        int i = tid + it * 128;                  // 0..1023
        int r = i >> 4;                          // row 0..63
        uint32_t cb = (uint32_t)((i & 15) * 8);  // byte col 0..120
        uint32_t sw = (uint32_t)(r * 128) + (cb ^ (uint32_t)((r & 7) << 4));
        float4 k = Kg[i], v = Vg[i];
        sts64(sb + OFF_KH + sw, pk(k.x, k.y), pk(k.z, k.w));
        sts64(sb + OFF_KL + sw, pk(bfr(k.x), bfr(k.y)), pk(bfr(k.z), bfr(k.w)));
        sts64(sb + OFF_VH + sw, pk(v.x, v.y), pk(v.z, v.w));
        sts64(sb + OFF_VL + sw, pk(bfr(v.x), bfr(v.y)), pk(bfr(v.z), bfr(v.w)));
    }
    __syncthreads();

    const int w    = tid >> 5;
    const int lane = tid & 31;
    const int g    = lane >> 2;
    const int t    = lane & 3;
    const int mb   = w * 16;
    const int rl   = lane & 7;          // ldmatrix row-within-tile
    const int lg8  = (lane >> 3) & 1;   // tile selector bits
    const int lg16 = lane >> 4;

    float acc[8][4];
    #pragma unroll
    for (int nt = 0; nt < 8; nt++) {
        acc[nt][0] = 0.f; acc[nt][1] = 0.f; acc[nt][2] = 0.f; acc[nt][3] = 0.f;
    }

    // ---- S = Q K^T : Q fragments direct from global, K via ldmatrix ----
    {
        const float* qr0 = Qg_ + base + (size_t)((mb + g) * 64 + 2 * t);
        const float* qr1 = qr0 + 8 * 64;
        // K ldmatrix per-lane address pieces: row = ntp*16 + lg16*8 + rl,
        // byte col = kt*32 + lg8*16, swizzled.
        #pragma unroll
        for (int kt = 0; kt < 4; kt++) {
            float2 q00 = *(const float2*)(qr0 + kt * 16);
            float2 q01 = *(const float2*)(qr0 + kt * 16 + 8);
            float2 q10 = *(const float2*)(qr1 + kt * 16);
            float2 q11 = *(const float2*)(qr1 + kt * 16 + 8);
            uint32_t a0h = pk(q00.x, q00.y), a1h = pk(q10.x, q10.y);
            uint32_t a2h = pk(q01.x, q01.y), a3h = pk(q11.x, q11.y);
            uint32_t a0l = pk(bfr(q00.x), bfr(q00.y)), a1l = pk(bfr(q10.x), bfr(q10.y));
            uint32_t a2l = pk(bfr(q01.x), bfr(q01.y)), a3l = pk(bfr(q11.x), bfr(q11.y));
            uint32_t cbyte = (uint32_t)(kt * 32 + lg8 * 16);
            #pragma unroll
            for (int ntp = 0; ntp < 4; ntp++) {
                int row = ntp * 16 + lg16 * 8 + rl;
                uint32_t addr = (uint32_t)(row * 128) + (cbyte ^ (uint32_t)((row & 7) << 4));
                uint32_t bh0, bh1, bh2, bh3, bl0, bl1, bl2, bl3;
                ldmx4(sb + OFF_KH + addr, bh0, bh1, bh2, bh3);
                ldmx4(sb + OFF_KL + addr, bl0, bl1, bl2, bl3);
                mma16(acc[2*ntp],   a0h, a1h, a2h, a3h, bh0, bh1);
                mma16(acc[2*ntp],   a0h, a1h, a2h, a3h, bl0, bl1);
                mma16(acc[2*ntp],   a0l, a1l, a2l, a3l, bh0, bh1);
                mma16(acc[2*ntp+1], a0h, a1h, a2h, a3h, bh2, bh3);
                mma16(acc[2*ntp+1], a0h, a1h, a2h, a3h, bl2, bl3);
                mma16(acc[2*ntp+1], a0l, a1l, a2l, a3l, bh2, bh3);
            }
        }
    }

    // ---- softmax (rows in-warp, quad shuffles) ----
    const float* kbias = (const float*)(sm + OFF_KB);
    const float* qm    = (const float*)(sm + OFF_QM);
    float m0 = -3.0e38f, m1 = -3.0e38f;
    #pragma unroll
    for (int nt = 0; nt < 8; nt++) {
        float2 kbv = *(const float2*)&kbias[nt * 8 + 2 * t];
        acc[nt][0] += kbv.x; acc[nt][1] += kbv.y;
        acc[nt][2] += kbv.x; acc[nt][3] += kbv.y;
        m0 = fmaxf(m0, fmaxf(acc[nt][0], acc[nt][1]));
        m1 = fmaxf(m1, fmaxf(acc[nt][2], acc[nt][3]));
    }
    m0 = fmaxf(m0, __shfl_xor_sync(0xffffffffu, m0, 1));
    m0 = fmaxf(m0, __shfl_xor_sync(0xffffffffu, m0, 2));
    m1 = fmaxf(m1, __shfl_xor_sync(0xffffffffu, m1, 1));
    m1 = fmaxf(m1, __shfl_xor_sync(0xffffffffu, m1, 2));
    float s0 = 0.f, s1 = 0.f;
    #pragma unroll
    for (int nt = 0; nt < 8; nt++) {
        acc[nt][0] = __expf(acc[nt][0] - m0);
        acc[nt][1] = __expf(acc[nt][1] - m0);
        acc[nt][2] = __expf(acc[nt][2] - m1);
        acc[nt][3] = __expf(acc[nt][3] - m1);
        s0 += acc[nt][0] + acc[nt][1];
        s1 += acc[nt][2] + acc[nt][3];
    }
    s0 += __shfl_xor_sync(0xffffffffu, s0, 1);
    s0 += __shfl_xor_sync(0xffffffffu, s0, 2);
    s1 += __shfl_xor_sync(0xffffffffu, s1, 1);
    s1 += __shfl_xor_sync(0xffffffffu, s1, 2);
    float r0 = (qm[mb + g]     == 0.0f) ? 0.0f : (1.0f / s0);
    float r1 = (qm[mb + g + 8] == 0.0f) ? 0.0f : (1.0f / s1);

    // ---- O = P V : P from registers, V via ldmatrix.trans ----
    float accO[8][4];
    #pragma unroll
    for (int nt = 0; nt < 8; nt++) {
        accO[nt][0] = 0.f; accO[nt][1] = 0.f; accO[nt][2] = 0.f; accO[nt][3] = 0.f;
    }
    #pragma unroll
    for (int kt = 0; kt < 4; kt++) {
        float s00 = acc[2*kt][0]   * r0, s01 = acc[2*kt][1]   * r0;
        float s10 = acc[2*kt][2]   * r1, s11 = acc[2*kt][3]   * r1;
        float s20 = acc[2*kt+1][0] * r0, s21 = acc[2*kt+1][1] * r0;
        float s30 = acc[2*kt+1][2] * r1, s31 = acc[2*kt+1][3] * r1;
        uint32_t a0h = pk(s00, s01), a1h = pk(s10, s11);
        uint32_t a2h = pk(s20, s21), a3h = pk(s30, s31);
        uint32_t a0l = pk(bfr(s00), bfr(s01)), a1l = pk(bfr(s10), bfr(s11));
        uint32_t a2l = pk(bfr(s20), bfr(s21)), a3l = pk(bfr(s30), bfr(s31));
        // V ldmatrix.trans: row = kt*16 + lg8*8 + rl, byte col = ntp*32 + lg16*16
        int vrow = kt * 16 + lg8 * 8 + rl;
        uint32_t vbase = (uint32_t)(vrow * 128);
        uint32_t vswx  = (uint32_t)((vrow & 7) << 4);
        #pragma unroll
        for (int ntp = 0; ntp < 4; ntp++) {
            uint32_t cbyte = (uint32_t)(ntp * 32 + lg16 * 16);
            uint32_t addr = vbase + (cbyte ^ vswx);
            uint32_t bh0, bh1, bh2, bh3, bl0, bl1, bl2, bl3;
            ldmx4t(sb + OFF_VH + addr, bh0, bh1, bh2, bh3);
            ldmx4t(sb + OFF_VL + addr, bl0, bl1, bl2, bl3);
            mma16(accO[2*ntp],   a0h, a1h, a2h, a3h, bh0, bh1);
            mma16(accO[2*ntp],   a0h, a1h, a2h, a3h, bl0, bl1);
            mma16(accO[2*ntp],   a0l, a1l, a2l, a3l, bh0, bh1);
            mma16(accO[2*ntp+1], a0h, a1h, a2h, a3h, bh2, bh3);
            mma16(accO[2*ntp+1], a0h, a1h, a2h, a3h, bl2, bl3);
            mma16(accO[2*ntp+1], a0l, a1l, a2l, a3l, bh2, bh3);
        }
    }

    // ---- store O (sector-aligned float2) ----
    float* Og = Og_ + base;
    #pragma unroll
    for (int nt = 0; nt < 8; nt++) {
        *(float2*)&Og[(mb + g)     * 64 + nt * 8 + 2 * t] = make_float2(accO[nt][0], accO[nt][1]);
        *(float2*)&Og[(mb + g + 8) * 64 + nt * 8 + 2 * t] = make_float2(accO[nt][2], accO[nt][3]);
    }
}

extern "C" void kernel_launch(void* const* d_in, const int* in_sizes, int n_in,
                              void* d_out, int out_size) {
    const float* Q = (const float*)d_in[0];
    const float* K = (const float*)d_in[1];
    const float* V = (const float*)d_in[2];
    const float* M = (const float*)d_in[3];
    float* O = (float*)d_out;
    cudaFuncSetAttribute(lsa4_kernel, cudaFuncAttributeMaxDynamicSharedMemorySize, SM_BYTES);
    lsa4_kernel<<<3072, 128, SM_BYTES>>>(Q, K, V, M, O);
}